// round 8
// baseline (speedup 1.0000x reference)
#include <cuda_runtime.h>
#include <math.h>

#define NTHREADS 512

// ---------------------------------------------------------------------------
// Scratch (device globals -- no allocation allowed)
// ---------------------------------------------------------------------------
__device__ float g_pred[(size_t)8 * 596 * 100 * 16];   // max: level 2, 30.5 MB
// S regions (S | S2) per level, disjoint:
//   L0: [0,2048)   L1: [2048,7168)   L2: [7168,32768)
// INVARIANT: all-zero at kernel entry; re-zeroed opportunistically during the
// run (each region only after its last reader has passed a grid barrier).
__device__ float g_S[32768];
__device__ unsigned g_bar_cnt;            // grid barrier arrival counter
__device__ volatile unsigned g_bar_gen;   // grid barrier generation (monotonic)

#define SOFF0 0
#define SOFF1 2048
#define SOFF2 7168

// ---------------------------------------------------------------------------
// Grid-wide barrier (all blocks resident: grid == #SMs, launch_bounds(512,1)).
// ---------------------------------------------------------------------------
__device__ __forceinline__ void grid_sync()
{
    __syncthreads();
    if (threadIdx.x == 0) {
        unsigned gen = g_bar_gen;                 // read BEFORE arriving
        __threadfence();                          // release this block's writes
        if (atomicAdd(&g_bar_cnt, 1u) == gridDim.x - 1) {
            atomicExch(&g_bar_cnt, 0u);
            __threadfence();
            g_bar_gen = gen + 1u;                 // release
        } else {
            while (g_bar_gen == gen) { }
            __threadfence();                      // acquire
        }
    }
    __syncthreads();
}

// ---------------------------------------------------------------------------
// squash of one 16-dim capsule (reads GLOBAL s, writes anywhere)
// ---------------------------------------------------------------------------
__device__ __forceinline__ void squash16(const float* __restrict__ s, float scale,
                                         float* __restrict__ out)
{
    float4 a[4];
    float sq = 0.f;
#pragma unroll
    for (int j = 0; j < 4; j++) {
        float4 t = __ldcg(reinterpret_cast<const float4*>(s) + j);
        t.x *= scale; t.y *= scale; t.z *= scale; t.w *= scale;
        sq += t.x*t.x + t.y*t.y + t.z*t.z + t.w*t.w;
        a[j] = t;
    }
    float f = sq / ((1.f + sq) * sqrtf(sq + 1e-7f));
#pragma unroll
    for (int j = 0; j < 4; j++) {
        a[j].x *= f; a[j].y *= f; a[j].z *= f; a[j].w *= f;
        reinterpret_cast<float4*>(out)[j] = a[j];
    }
}

// ---------------------------------------------------------------------------
// pred phase: pred[b,i,c,d] = sum_k W[i,c,d,k] * Xlvl[b,i,k]
// + S[b,c,d] accumulation. Virtual-block grid-stride loop.
// Xlvl: i<skip -> X (per-b block of 9216 floats); else shared vbuf.
// ---------------------------------------------------------------------------
template<int N, int C, int K, int IPAR, int ILOOP, int CTILE>
__device__ void pred_phase(const float* __restrict__ X,
                           const float* __restrict__ W,
                           const float* __restrict__ vbuf,   // shared
                           int skip, int cprev, int soff, float* Xs)
{
    constexpr int ICHUNK = IPAR * ILOOP;
    constexpr int ACTIVE = IPAR * CTILE * 16;
    constexpr int K4     = K / 4;
    constexpr int NCHUNK = N / ICHUNK;                 // exact for our sizes
    constexpr int CTILES = (C + CTILE - 1) / CTILE;
    const int tid = threadIdx.x;

    for (int vb = blockIdx.x; vb < NCHUNK * CTILES; vb += gridDim.x) {
        const int chunk = vb % NCHUNK;
        const int ct    = vb / NCHUNK;
        const int i0    = chunk * ICHUNK;

        for (int idx = tid; idx < ICHUNK * 8 * K; idx += NTHREADS) {
            int il = idx / (8 * K);
            int r  = idx % (8 * K);
            int b  = r / K, k = r % K;
            int gi = i0 + il;
            Xs[idx] = (gi < skip) ? X[b * 9216 + gi * K + k]
                                  : vbuf[(b * cprev + (gi - skip)) * 16 + k];
        }
        __syncthreads();

        if (tid < ACTIVE) {
            const int isub  = tid / (CTILE * 16);
            const int rem   = tid % (CTILE * 16);
            const int c     = ct * CTILE + rem / 16;
            const int d     = rem % 16;
            const int ibase = isub * ILOOP;

            float acc[8];
#pragma unroll
            for (int b = 0; b < 8; b++) acc[b] = 0.f;

            float4 wc[K4];
            {
                const float* wp = W + ((size_t)((i0 + ibase) * C + c) * 16 + d) * K;
#pragma unroll
                for (int k4 = 0; k4 < K4; k4++)
                    wc[k4] = __ldcg(reinterpret_cast<const float4*>(wp) + k4);
            }
#pragma unroll
            for (int il2 = 0; il2 < ILOOP; ++il2) {
                float4 wn[K4];
                if (il2 + 1 < ILOOP) {
                    const float* wp =
                        W + ((size_t)((i0 + ibase + il2 + 1) * C + c) * 16 + d) * K;
#pragma unroll
                    for (int k4 = 0; k4 < K4; k4++)
                        wn[k4] = __ldcg(reinterpret_cast<const float4*>(wp) + k4);
                }
                const int iloc = ibase + il2;
                const int i    = i0 + iloc;
                float w[K];
#pragma unroll
                for (int k4 = 0; k4 < K4; k4++) {
                    w[4*k4+0] = wc[k4].x; w[4*k4+1] = wc[k4].y;
                    w[4*k4+2] = wc[k4].z; w[4*k4+3] = wc[k4].w;
                }
                const float* xrow = Xs + iloc * 8 * K;
#pragma unroll
                for (int b = 0; b < 8; b++) {
                    float p = 0.f;
#pragma unroll
                    for (int k = 0; k < K; k++) p += w[k] * xrow[b * K + k];
                    acc[b] += p;
                    __stcg(&g_pred[(((size_t)b * N + i) * C + c) * 16 + d], p);
                }
#pragma unroll
                for (int k4 = 0; k4 < K4; k4++) wc[k4] = wn[k4];
            }
#pragma unroll
            for (int b = 0; b < 8; b++)
                atomicAdd(&g_S[soff + (b * C + c) * 16 + d], acc[b]);
        }
        __syncthreads();
    }
}

// ---------------------------------------------------------------------------
// The whole network in one persistent cooperative kernel.
// ---------------------------------------------------------------------------
extern "C" __global__ void __launch_bounds__(NTHREADS, 1)
caps_kernel(const float* __restrict__ X,
            const float* __restrict__ W0,
            const float* __restrict__ W1,
            const float* __restrict__ W2,
            float* __restrict__ v0, float* __restrict__ v1, float* __restrict__ v2)
{
    extern __shared__ float sm[];
    const int tid  = threadIdx.x, lane = tid & 31, wid = tid >> 5;
    const int nb   = gridDim.x;
    const int b8   = blockIdx.x & 7;
    const int nb_b   = (nb - b8 + 7) >> 3;            // blocks with this b
    const int stride = nb_b * 16;                     // warp stripes per b
    const int stripe = (blockIdx.x >> 3) * 16 + wid;

    // ---------------- P0: pred level 0 ----------------
    pred_phase<1152, 8, 8, 4, 2, 8>(X, W0, nullptr, 1152, 1, SOFF0, sm);
    grid_sync();

    // ---------------- P1: route level 0 (C=8, CD=128) ----------------
    {
        float* vsh = sm;                              // 128 floats (this b)
        if (tid < 8)
            squash16(&g_S[SOFF0 + b8 * 128 + tid * 16], 0.125f, &vsh[tid * 16]);
        __syncthreads();
        const float4 v4 = *reinterpret_cast<const float4*>(&vsh[lane * 4]);
        float ax = 0.f, ay = 0.f, az = 0.f, aw = 0.f;
        for (int i = stripe; i < 1152; i += stride) {
            float4 p = __ldcg(reinterpret_cast<const float4*>(
                g_pred + ((size_t)(b8 * 1152 + i)) * 128 + lane * 4));
            float lg = p.x*v4.x + p.y*v4.y + p.z*v4.z + p.w*v4.w;
            lg += __shfl_xor_sync(~0u, lg, 1);
            lg += __shfl_xor_sync(~0u, lg, 2);        // logit for c = lane/4
            float e = __expf(lg);
            float s = e;
            s += __shfl_xor_sync(~0u, s, 4);
            s += __shfl_xor_sync(~0u, s, 8);
            s += __shfl_xor_sync(~0u, s, 16);         // = sum_c e_c
            float w = e / s;
            ax += w * p.x; ay += w * p.y; az += w * p.z; aw += w * p.w;
        }
        float* S2 = &g_S[SOFF0 + 1024 + b8 * 128 + lane * 4];
        atomicAdd(S2 + 0, ax); atomicAdd(S2 + 1, ay);
        atomicAdd(S2 + 2, az); atomicAdd(S2 + 3, aw);
    }
    grid_sync();

    // ---------------- P2: pred level 1 (+ write v0) ----------------
    {
        float* Xs   = sm;                             // 512 floats
        float* vbuf = sm + 512;                       // 1024 floats (v0, all b)
        if (tid < 64)
            squash16(&g_S[SOFF0 + 1024 + tid * 16], 1.f, &vbuf[tid * 16]);
        __syncthreads();
        if (blockIdx.x == 0)
            for (int e = tid; e < 1024; e += NTHREADS) v0[e] = vbuf[e];
        pred_phase<584, 20, 16, 1, 4, 20>(X, W1, vbuf, 576, 8, SOFF1, Xs);
    }
    grid_sync();

    // ---------------- P3: route level 1 (C=20, CD=320) + zero S0 ----------------
    {
        float* vsh = sm;                              // 320 floats (this b)
        if (tid < 20)
            squash16(&g_S[SOFF1 + b8 * 320 + tid * 16], 0.05f, &vsh[tid * 16]);
        __syncthreads();
        if (blockIdx.x == nb - 1)
            for (int e = tid; e < 2048; e += NTHREADS) g_S[SOFF0 + e] = 0.f;

        float v[10], acc[10];
#pragma unroll
        for (int cc = 0; cc < 10; cc++) { v[cc] = vsh[32*cc + lane]; acc[cc] = 0.f; }

        for (int i = stripe; i < 584; i += stride) {
            const float* pb = g_pred + ((size_t)(b8 * 584 + i)) * 320;
            float p[10], lg[10];
#pragma unroll
            for (int cc = 0; cc < 10; cc++) {
                p[cc] = __ldcg(pb + 32 * cc + lane);
                float t = p[cc] * v[cc];
                t += __shfl_xor_sync(~0u, t, 1);
                t += __shfl_xor_sync(~0u, t, 2);
                t += __shfl_xor_sync(~0u, t, 4);
                t += __shfl_xor_sync(~0u, t, 8);
                lg[cc] = t;
            }
            float tot = 0.f;
#pragma unroll
            for (int cc = 0; cc < 10; cc++) { lg[cc] = __expf(lg[cc]); tot += lg[cc]; }
            tot += __shfl_xor_sync(~0u, tot, 16);
            float inv = 1.f / tot;
#pragma unroll
            for (int cc = 0; cc < 10; cc++) acc[cc] += lg[cc] * inv * p[cc];
        }
#pragma unroll
        for (int cc = 0; cc < 10; cc++)
            atomicAdd(&g_S[SOFF1 + 2560 + b8 * 320 + 32 * cc + lane], acc[cc]);
    }
    grid_sync();

    // ---------------- P4: pred level 2 (+ write v1) ----------------
    {
        float* Xs   = sm;                             // 512 floats
        float* vbuf = sm + 512;                       // 2560 floats (v1, all b)
        if (tid < 160)
            squash16(&g_S[SOFF1 + 2560 + tid * 16], 1.f, &vbuf[tid * 16]);
        __syncthreads();
        if (blockIdx.x == 0)
            for (int e = tid; e < 2560; e += NTHREADS) v1[e] = vbuf[e];
        pred_phase<596, 100, 16, 1, 4, 25>(X, W2, vbuf, 576, 20, SOFF2, Xs);
    }
    grid_sync();

    // ---------------- P5: route level 2 (C=100, CD=1600) + zero S1 ----------------
    {
        float* vsh     = sm;                          // 1600 (this b)
        float* slogAll = sm + 1600;                   // 16*100
        float* saccAll = sm + 3200;                   // 16*1600
        if (tid < 100)
            squash16(&g_S[SOFF2 + b8 * 1600 + tid * 16], 0.01f, &vsh[tid * 16]);
        for (int e = tid; e < 16 * 1600; e += NTHREADS) saccAll[e] = 0.f;
        __syncthreads();
        if (blockIdx.x == nb - 1)
            for (int e = tid; e < 5120; e += NTHREADS) g_S[SOFF1 + e] = 0.f;

        float* sa = saccAll + wid * 1600;
        float* sl = slogAll + wid * 100;
        const int half = lane >> 4;

        for (int i = stripe; i < 596; i += stride) {
            const float* pb = g_pred + ((size_t)(b8 * 596 + i)) * 1600;
            float p[50];
#pragma unroll
            for (int cc = 0; cc < 50; cc++) {
                p[cc] = __ldcg(pb + 32 * cc + lane);
                float t = p[cc] * vsh[32 * cc + lane];
                t += __shfl_xor_sync(~0u, t, 1);
                t += __shfl_xor_sync(~0u, t, 2);
                t += __shfl_xor_sync(~0u, t, 4);
                t += __shfl_xor_sync(~0u, t, 8);
                if ((lane & 15) == 0) sl[2 * cc + half] = t;   // logit c=2cc+half
            }
            __syncwarp();
            // distributed softmax over 100 logits (bounded; no max needed)
            float e0 = __expf(sl[lane]);
            float e1 = __expf(sl[lane + 32]);
            float e2 = __expf(sl[lane + 64]);
            float e3 = (lane < 4) ? __expf(sl[lane + 96]) : 0.f;
            float tot = e0 + e1 + e2 + e3;
#pragma unroll
            for (int o = 16; o; o >>= 1) tot += __shfl_xor_sync(~0u, tot, o);
            sl[lane] = e0; sl[lane + 32] = e1; sl[lane + 64] = e2;
            if (lane < 4) sl[lane + 96] = e3;
            __syncwarp();
            float inv = 1.f / tot;
#pragma unroll
            for (int cc = 0; cc < 50; cc++)
                sa[32 * cc + lane] += sl[2 * cc + half] * inv * p[cc];
        }
        __syncthreads();
        for (int e = tid; e < 1600; e += NTHREADS) {
            float s = 0.f;
#pragma unroll
            for (int w = 0; w < 16; w++) s += saccAll[w * 1600 + e];
            atomicAdd(&g_S[SOFF2 + 12800 + b8 * 1600 + e], s);
        }
    }
    grid_sync();

    // ---------------- P6: final squash v2 + restore S2 zeros ----------------
    if (blockIdx.x == 0) {
        for (int cap = tid; cap < 800; cap += NTHREADS)
            squash16(&g_S[SOFF2 + 12800 + cap * 16], 1.f, v2 + cap * 16);
        __syncthreads();
        for (int e = tid; e < 12800; e += NTHREADS) g_S[SOFF2 + 12800 + e] = 0.f;
    } else {
        for (int e = (blockIdx.x - 1) * NTHREADS + tid; e < 12800;
             e += (nb - 1) * NTHREADS)
            g_S[SOFF2 + e] = 0.f;
    }
}

// ---------------------------------------------------------------------------
extern "C" void kernel_launch(void* const* d_in, const int* in_sizes, int n_in,
                              void* d_out, int out_size)
{
    const float* X  = (const float*)d_in[0];   // [8,1152,8]
    const float* W0 = (const float*)d_in[1];   // [1152,8,16,8]
    const float* W1 = (const float*)d_in[2];   // [584,20,16,16]
    const float* W2 = (const float*)d_in[3];   // [596,100,16,16]
    float* out = (float*)d_out;
    float* v0 = out;                 // [8][8][16]
    float* v1 = out + 1024;          // [8][20][16]
    float* v2 = out + 3584;          // [8][100][16]

    int sms = 148;
    cudaDeviceGetAttribute(&sms, cudaDevAttrMultiProcessorCount, 0);
    if (sms > 148) sms = 148;        // virtual grids sized for <=148

    const int smem_bytes = (3200 + 16 * 1600) * 4;   // 115200 B
    cudaFuncSetAttribute(caps_kernel,
                         cudaFuncAttributeMaxDynamicSharedMemorySize, smem_bytes);

    caps_kernel<<<sms, NTHREADS, smem_bytes>>>(X, W0, W1, W2, v0, v1, v2);
}